// round 5
// baseline (speedup 1.0000x reference)
#include <cuda_runtime.h>

// TensorProduct: out[n,p3,k,f] from x1[n,p1,l,f], x2[n,p2,m,f], cg[l,m,k]
//   out_even = couple(x1_e,x2_e) + couple(x1_o,x2_o)
//   out_odd  = couple(x1_e,x2_o) + couple(x1_o,x2_e)
// N=50000, F=128, L1=L2=9, L3=25.
// One thread = one (node, float2-channel-pair). Packed f32x2 FMAs (FFMA2)
// for 2x scalar-FMA throughput; compile-time unrolled triangle-rule loops
// (1225 nonzero (l,m,k) triples, contiguous k-range per (l,m)).

typedef unsigned long long u64;

#define NLM 9
#define NK  25
#define F2  64   // 128 channels as 64 float2 pairs

__device__ __forceinline__ u64 fma2(u64 a, u64 b, u64 c) {
    u64 d;
    asm("fma.rn.f32x2 %0, %1, %2, %3;" : "=l"(d) : "l"(a), "l"(b), "l"(c));
    return d;
}
__device__ __forceinline__ u64 mul2(u64 a, u64 b) {
    u64 d;
    asm("mul.rn.f32x2 %0, %1, %2;" : "=l"(d) : "l"(a), "l"(b));
    return d;
}

__global__ __launch_bounds__(256)
void tp_kernel(const float* __restrict__ x1,
               const float* __restrict__ x2,
               const float* __restrict__ cg,
               float* __restrict__ out,
               int nthreads)
{
    // cg duplicated into (v,v) u64 so a single broadcast LDS.64 feeds FFMA2.
    __shared__ u64 cgs[NLM * NLM * NK];   // 2025 * 8 B = 16.2 KB
    for (int i = threadIdx.x; i < NLM * NLM * NK; i += blockDim.x) {
        float v = cg[i];
        u64 d;
        asm("mov.b64 %0, {%1, %1};" : "=l"(d) : "f"(v));
        cgs[i] = d;
    }
    __syncthreads();

    int t = blockIdx.x * blockDim.x + threadIdx.x;
    if (t >= nthreads) return;
    int c = t & (F2 - 1);          // float2 channel pair
    int n = t >> 6;                // node

    const u64* x1p = (const u64*)x1 + (size_t)n * (2 * NLM * F2) + c;
    const u64* x2p = (const u64*)x2 + (size_t)n * (2 * NLM * F2) + c;

    // Preload x1 even/odd rows (18 x LDG.64)
    u64 ae[NLM], ao[NLM];
#pragma unroll
    for (int l = 0; l < NLM; ++l) {
        ae[l] = x1p[l * F2];
        ao[l] = x1p[(NLM + l) * F2];
    }

    u64 acce[NK], acco[NK];
#pragma unroll
    for (int k = 0; k < NK; ++k) { acce[k] = 0ull; acco[k] = 0ull; }

    constexpr int LDEG[NLM] = {0, 1, 1, 1, 2, 2, 2, 2, 2};  // l = floor(sqrt(i))

#pragma unroll
    for (int m = 0; m < NLM; ++m) {
        u64 be = x2p[m * F2];
        u64 bo = x2p[(NLM + m) * F2];
#pragma unroll
        for (int l = 0; l < NLM; ++l) {
            // parity-combined products
            u64 pe = fma2(ae[l], be, mul2(ao[l], bo));  // even output source
            u64 po = fma2(ae[l], bo, mul2(ao[l], be));  // odd  output source

            const int l1 = LDEG[l], l2 = LDEG[m];
            const int lo = (l1 > l2) ? (l1 - l2) : (l2 - l1);
            const int hi = l1 + l2;
            const int klo = lo * lo;             // first allowed flattened k
            const int khi = (hi + 1) * (hi + 1); // one past last allowed k
#pragma unroll
            for (int k = 0; k < NK; ++k) {
                if (k >= klo && k < khi) {       // compile-time pruned
                    u64 w = cgs[(l * NLM + m) * NK + k];
                    acce[k] = fma2(w, pe, acce[k]);
                    acco[k] = fma2(w, po, acco[k]);
                }
            }
        }
    }

    u64* op = (u64*)out + (size_t)n * (2 * NK * F2) + c;
#pragma unroll
    for (int k = 0; k < NK; ++k) {
        op[k * F2]        = acce[k];
        op[(NK + k) * F2] = acco[k];
    }
}

extern "C" void kernel_launch(void* const* d_in, const int* in_sizes, int n_in,
                              void* d_out, int out_size)
{
    const float* x1 = (const float*)d_in[0];
    const float* x2 = (const float*)d_in[1];
    const float* cg = (const float*)d_in[2];
    float* out = (float*)d_out;

    // each thread writes 50 float2 = 100 output floats
    int nthreads = out_size / 100;           // = N * 64 = 3,200,000
    int block = 256;
    int grid = (nthreads + block - 1) / block;
    tp_kernel<<<grid, block>>>(x1, x2, cg, out, nthreads);
}